// round 7
// baseline (speedup 1.0000x reference)
#include <cuda_runtime.h>

#define SIZE 512
#define NS 256
#define BX 16
#define BY 16
#define NT 128

__device__ __forceinline__ float fsqrt_approx(float x) {
    float r; asm("sqrt.approx.f32 %0, %1;" : "=f"(r) : "f"(x)); return r;
}
__device__ __forceinline__ float fexp2_approx(float x) {
    float r; asm("ex2.approx.f32 %0, %1;" : "=f"(r) : "f"(x)); return r;
}
__device__ __forceinline__ float flog2_approx(float x) {
    float r; asm("lg2.approx.f32 %0, %1;" : "=f"(r) : "f"(x)); return r;
}
__device__ __forceinline__ float frcp_approx(float x) {
    float r; asm("rcp.approx.f32 %0, %1;" : "=f"(r) : "f"(x)); return r;
}

__device__ __forceinline__ float2 bezier_sample(const float4* __restrict__ cp4, int idx) {
    const int stroke = idx >> 5;
    const int j = idx & 31;
    const float t  = (float)j * (1.0f / 31.0f);
    const float mt = 1.0f - t;
    const float4 a = cp4[2 * stroke];       // p0x p0y p1x p1y
    const float4 b = cp4[2 * stroke + 1];   // p2x p2y p3x p3y
    const float w0 = mt * mt * mt;
    const float w1 = 3.0f * mt * mt * t;
    const float w2 = 3.0f * mt * t * t;
    const float w3 = t * t * t;
    const float sx = w0 * __saturatef(a.x) + w1 * __saturatef(a.z)
                   + w2 * __saturatef(b.x) + w3 * __saturatef(b.z);
    const float sy = w0 * __saturatef(a.y) + w1 * __saturatef(a.w)
                   + w2 * __saturatef(b.y) + w3 * __saturatef(b.w);
    return make_float2(sx, sy);
}

__global__ __launch_bounds__(NT)
void glyph_kernel(const float* __restrict__ cp, float* __restrict__ out)
{
    __shared__ float2 keep[NS + 4];
    __shared__ float  wmin[4];
    __shared__ int    cnt[8];

    const int tid  = threadIdx.x;
    const int lane = tid & 31;
    const int w    = tid >> 5;

    const int x0 = blockIdx.x * BX;
    const int y0 = blockIdx.y * BY;

    const float inv = 1.0f / 511.0f;
    const float cx = ((float)x0 + 7.5f) * inv;
    const float cy = ((float)y0 + 7.5f) * inv;
    const float r  = 0.020758f + 1e-4f;    // 0.5*sqrt(15^2+15^2)/511

    // ---- per-block Bezier samples (2 per thread) + center dist^2 ----
    const float4* cp4 = (const float4*)cp;
    const float2 sA = bezier_sample(cp4, tid);
    const float2 sB = bezier_sample(cp4, tid + NT);
    float dx = cx - sA.x, dy = cy - sA.y;
    const float dc2A = fmaf(dx, dx, dy * dy);
    dx = cx - sB.x; dy = cy - sB.y;
    const float dc2B = fmaf(dx, dx, dy * dy);

    {
        const int rm = __reduce_min_sync(0xffffffffu,
                                         __float_as_int(fminf(dc2A, dc2B)));
        if (lane == 0) wmin[w] = __int_as_float(rm);
    }
    __syncthreads();
    const float dcmin = sqrtf(fminf(fminf(wmin[0], wmin[1]), fminf(wmin[2], wmin[3])));

    // two pixels per thread: (px, py) and (px, py+8)
    const int px = x0 + (tid & 15);
    const int py = y0 + (tid >> 4);
    const int p1 = py * SIZE + px;
    const int p2 = p1 + 8 * SIZE;

    // ---- whole-block skip: coverage < 2.3e-5 ----
    if (dcmin > 0.115f + r) {
        out[p1] = 1.0f;
        out[p2] = 1.0f;
        return;
    }

    // ---- block compaction: keep dc <= dcmin + 2r + 0.055 ----
    const float thr  = dcmin + 2.0f * r + 0.055f;
    const float thr2 = thr * thr;
    const bool kA = (dc2A <= thr2);
    const bool kB = (dc2B <= thr2);
    const unsigned mA = __ballot_sync(0xffffffffu, kA);
    const unsigned mB = __ballot_sync(0xffffffffu, kB);
    if (lane == 0) { cnt[2 * w] = __popc(mA); cnt[2 * w + 1] = __popc(mB); }
    __syncthreads();
    int off[9];
    off[0] = 0;
    #pragma unroll
    for (int i = 0; i < 8; i++) off[i + 1] = off[i] + cnt[i];
    const int n = off[8];
    const unsigned lt = (1u << lane) - 1u;
    if (kA) keep[off[2 * w]     + __popc(mA & lt)] = sA;
    if (kB) keep[off[2 * w + 1] + __popc(mB & lt)] = sB;
    if (tid < 4) keep[n + tid] = make_float2(100.0f, 100.0f);   // sentinels
    __syncthreads();
    const int n4 = (n + 3) & ~3;

    // ---- per-pixel single-pass soft-min, 2 pixels per thread (2x ILP) ----
    const float gx  = (float)px * inv;
    const float gy1 = (float)py * inv;
    const float dgy = 8.0f * inv;
    const float NEGK = -369.3298503f;       // -256 * log2(e)
    const float4* kp4 = (const float4*)keep;
    float acc1 = 0.0f, acc2 = 0.0f;
    #pragma unroll 4
    for (int i = 0; i < (n4 >> 1); i++) {
        const float4 q = kp4[i];
        // sample (q.x,q.y)
        float ax = gx - q.x;
        float ay = gy1 - q.y;
        float ay2 = ay + dgy;
        acc1 += fexp2_approx(fsqrt_approx(fmaf(ax, ax, ay * ay)) * NEGK);
        acc2 += fexp2_approx(fsqrt_approx(fmaf(ax, ax, ay2 * ay2)) * NEGK);
        // sample (q.z,q.w)
        ax = gx - q.z;
        ay = gy1 - q.w;
        ay2 = ay + dgy;
        acc1 += fexp2_approx(fsqrt_approx(fmaf(ax, ax, ay * ay)) * NEGK);
        acc2 += fexp2_approx(fsqrt_approx(fmaf(ax, ax, ay2 * ay2)) * NEGK);
    }

    const float C1 = -0.69314718f / 256.0f;
    const float C2 = 200.0f * 1.44269504f;
    const float md1 = flog2_approx(acc1) * C1;
    const float md2 = flog2_approx(acc2) * C1;
    const float e1 = fexp2_approx((0.04f - md1) * C2);
    const float e2 = fexp2_approx((0.04f - md2) * C2);
    out[p1] = frcp_approx(1.0f + e1);
    out[p2] = frcp_approx(1.0f + e2);
}

extern "C" void kernel_launch(void* const* d_in, const int* in_sizes, int n_in,
                              void* d_out, int out_size) {
    const float* cp = (const float*)d_in[0];   // control_points [8,4,2]
    float* out = (float*)d_out;
    dim3 gridDim(SIZE / BX, SIZE / BY);        // 32 x 32 = 1024 blocks
    glyph_kernel<<<gridDim, NT>>>(cp, out);
}

// round 8
// speedup vs baseline: 1.4030x; 1.4030x over previous
#include <cuda_runtime.h>

#define SIZE 512
#define NS 256
#define NT 128
#define KST4 130     // per-warp keep stride in float4 (260 float2 >= 256+2 sentinels)

__device__ float4 g_samples4[NS / 2];

__device__ __forceinline__ float fsqrt_approx(float x) {
    float r; asm("sqrt.approx.f32 %0, %1;" : "=f"(r) : "f"(x)); return r;
}
__device__ __forceinline__ float fexp2_approx(float x) {
    float r; asm("ex2.approx.f32 %0, %1;" : "=f"(r) : "f"(x)); return r;
}
__device__ __forceinline__ float flog2_approx(float x) {
    float r; asm("lg2.approx.f32 %0, %1;" : "=f"(r) : "f"(x)); return r;
}
__device__ __forceinline__ float frcp_approx(float x) {
    float r; asm("rcp.approx.f32 %0, %1;" : "=f"(r) : "f"(x)); return r;
}

// ---- setup: compute the 256 clamped Bezier samples once ----
__global__ void sample_kernel(const float* __restrict__ cp) {
    const int tid = threadIdx.x;          // 0..255
    const int stroke = tid >> 5;
    const int j = tid & 31;
    const float t  = (float)j * (1.0f / 31.0f);
    const float mt = 1.0f - t;
    const float* c = cp + stroke * 8;
    const float w0 = mt * mt * mt;
    const float w1 = 3.0f * mt * mt * t;
    const float w2 = 3.0f * mt * t * t;
    const float w3 = t * t * t;
    const float sx = w0 * __saturatef(c[0]) + w1 * __saturatef(c[2])
                   + w2 * __saturatef(c[4]) + w3 * __saturatef(c[6]);
    const float sy = w0 * __saturatef(c[1]) + w1 * __saturatef(c[3])
                   + w2 * __saturatef(c[5]) + w3 * __saturatef(c[7]);
    ((float2*)g_samples4)[tid] = make_float2(sx, sy);
}

// ---- main: 4 independent warps per CTA, one 8x4 pixel tile per warp ----
__global__ __launch_bounds__(NT)
void glyph_kernel(float* __restrict__ out)
{
    __shared__ float4 samp[NS / 2];          // 2 KB, shared by all 4 warps
    __shared__ float4 keepbuf[4 * KST4];     // 8.3 KB, private segment per warp

    const int tid  = threadIdx.x;
    const int lane = tid & 31;
    const int w    = tid >> 5;

    // stage the 256 samples once per CTA (coalesced LDG.128 -> STS.128)
    samp[tid] = g_samples4[tid];
    __syncthreads();
    // from here on, warps are fully independent

    const int tile = blockIdx.x * 4 + w;     // 0..8191
    const int x0 = (tile & 63) * 8;          // 64 x-tiles of 8 px
    const int y0 = (tile >> 6) * 4;          // 128 y-tiles of 4 px

    const float inv = 1.0f / 511.0f;
    const float cx = ((float)x0 + 3.5f) * inv;
    const float cy = ((float)y0 + 1.5f) * inv;
    const float r  = 0.0074617f + 1e-4f;     // 0.5*sqrt(7^2+3^2)/511

    // ---- 8 samples per lane: center dist^2 + warp-min ----
    float2 s[8];
    float  dc2[8];
    float  m = 1e30f;
    #pragma unroll
    for (int j = 0; j < 4; j++) {
        const float4 v = samp[j * 32 + lane];
        s[2 * j]     = make_float2(v.x, v.y);
        s[2 * j + 1] = make_float2(v.z, v.w);
        float ax = cx - v.x, ay = cy - v.y;
        dc2[2 * j] = fmaf(ax, ax, ay * ay);
        ax = cx - v.z; ay = cy - v.w;
        dc2[2 * j + 1] = fmaf(ax, ax, ay * ay);
        m = fminf(m, fminf(dc2[2 * j], dc2[2 * j + 1]));
    }
    #pragma unroll
    for (int off = 16; off; off >>= 1)
        m = fminf(m, __shfl_xor_sync(0xffffffffu, m, off));
    const float dcmin = sqrtf(m);

    const int px = x0 + (lane & 7);
    const int py = y0 + (lane >> 3);
    const int p  = py * SIZE + px;

    // ---- warp-tile skip: coverage < 2.3e-5 ----
    if (dcmin > 0.115f + r) {
        out[p] = 1.0f;
        return;
    }

    // ---- warp compaction: keep dc <= dcmin + 2r + 0.055 ----
    const float thr  = dcmin + 2.0f * r + 0.055f;
    const float thr2 = thr * thr;
    float2* kp = (float2*)(keepbuf + w * KST4);
    const unsigned lt = (1u << lane) - 1u;
    int c = 0;
    #pragma unroll
    for (int j = 0; j < 8; j++) {
        const bool k = (dc2[j] <= thr2);
        const unsigned msk = __ballot_sync(0xffffffffu, k);
        if (k) kp[c + __popc(msk & lt)] = s[j];
        c += __popc(msk);
    }
    if (lane < 2) kp[c + lane] = make_float2(100.0f, 100.0f);  // sentinels
    __syncwarp();
    const int nIt = (c + 1) >> 1;            // float4 (2-sample) iterations

    // ---- per-pixel single-pass soft-min (1 pixel per lane) ----
    const float gx = (float)px * inv;
    const float gy = (float)py * inv;
    const float NEGK = -369.3298503f;        // -256 * log2(e)
    const float4* kp4 = (const float4*)kp;
    float acc = 0.0f;
    #pragma unroll 4
    for (int i = 0; i < nIt; i++) {
        const float4 q = kp4[i];             // broadcast LDS.128
        float ax = gx - q.x, ay = gy - q.y;
        const float dA = fsqrt_approx(fmaf(ax, ax, ay * ay));
        ax = gx - q.z; ay = gy - q.w;
        const float dB = fsqrt_approx(fmaf(ax, ax, ay * ay));
        acc += fexp2_approx(dA * NEGK);
        acc += fexp2_approx(dB * NEGK);
    }

    const float md = flog2_approx(acc) * (-0.69314718f / 256.0f);
    const float z  = (0.04f - md) * (200.0f * 1.44269504f);
    out[p] = frcp_approx(1.0f + fexp2_approx(z));
}

extern "C" void kernel_launch(void* const* d_in, const int* in_sizes, int n_in,
                              void* d_out, int out_size) {
    const float* cp = (const float*)d_in[0];   // control_points [8,4,2]
    float* out = (float*)d_out;
    sample_kernel<<<1, NS>>>(cp);
    glyph_kernel<<<2048, NT>>>(out);           // 2048 CTAs x 4 warp-tiles
}

// round 9
// speedup vs baseline: 1.7279x; 1.2316x over previous
#include <cuda_runtime.h>

#define SIZE 512
#define NS 256
#define NT 128
#define KST4 132     // per-warp keep stride in float4 (264 float2 >= 256+4 sentinels)

__device__ __forceinline__ float fsqrt_approx(float x) {
    float r; asm("sqrt.approx.f32 %0, %1;" : "=f"(r) : "f"(x)); return r;
}
__device__ __forceinline__ float fexp2_approx(float x) {
    float r; asm("ex2.approx.f32 %0, %1;" : "=f"(r) : "f"(x)); return r;
}
__device__ __forceinline__ float flog2_approx(float x) {
    float r; asm("lg2.approx.f32 %0, %1;" : "=f"(r) : "f"(x)); return r;
}
__device__ __forceinline__ float frcp_approx(float x) {
    float r; asm("rcp.approx.f32 %0, %1;" : "=f"(r) : "f"(x)); return r;
}

// ---- fused single kernel: 4 independent warps per CTA, one 8x4 tile per warp ----
__global__ __launch_bounds__(NT)
void glyph_kernel(const float* __restrict__ cp, float* __restrict__ out)
{
    __shared__ float4 samp[NS / 2];          // 2 KB: 256 samples as 128 float4 pairs
    __shared__ float4 keepbuf[4 * KST4];     // private segment per warp

    const int tid  = threadIdx.x;
    const int lane = tid & 31;
    const int w    = tid >> 5;

    // ---- per-CTA Bezier samples: thread t computes samples 2t and 2t+1 ----
    {
        const float4* cp4 = (const float4*)cp;
        const int stroke = tid >> 4;                  // (2*tid)>>5
        const float4 a = cp4[2 * stroke];             // p0x p0y p1x p1y
        const float4 b = cp4[2 * stroke + 1];         // p2x p2y p3x p3y
        const float q0x = __saturatef(a.x), q0y = __saturatef(a.y);
        const float q1x = __saturatef(a.z), q1y = __saturatef(a.w);
        const float q2x = __saturatef(b.x), q2y = __saturatef(b.y);
        const float q3x = __saturatef(b.z), q3y = __saturatef(b.w);
        const int j = (2 * tid) & 31;
        float4 o;
        {
            const float t  = (float)j * (1.0f / 31.0f);
            const float mt = 1.0f - t;
            const float w0 = mt * mt * mt, w1 = 3.0f * mt * mt * t;
            const float w2 = 3.0f * mt * t * t, w3 = t * t * t;
            o.x = w0 * q0x + w1 * q1x + w2 * q2x + w3 * q3x;
            o.y = w0 * q0y + w1 * q1y + w2 * q2y + w3 * q3y;
        }
        {
            const float t  = (float)(j + 1) * (1.0f / 31.0f);
            const float mt = 1.0f - t;
            const float w0 = mt * mt * mt, w1 = 3.0f * mt * mt * t;
            const float w2 = 3.0f * mt * t * t, w3 = t * t * t;
            o.z = w0 * q0x + w1 * q1x + w2 * q2x + w3 * q3x;
            o.w = w0 * q0y + w1 * q1y + w2 * q2y + w3 * q3y;
        }
        samp[tid] = o;
    }
    __syncthreads();
    // from here on, warps are fully independent

    const int tile = blockIdx.x * 4 + w;     // 0..8191
    const int x0 = (tile & 63) * 8;          // 64 x-tiles of 8 px
    const int y0 = (tile >> 6) * 4;          // 128 y-tiles of 4 px

    const float inv = 1.0f / 511.0f;
    const float cx = ((float)x0 + 3.5f) * inv;
    const float cy = ((float)y0 + 1.5f) * inv;
    const float r  = 0.0074617f + 1e-4f;     // 0.5*sqrt(7^2+3^2)/511

    // ---- 8 samples per lane: center dist^2 + warp-min ----
    float2 s[8];
    float  dc2[8];
    float  m = 1e30f;
    #pragma unroll
    for (int j = 0; j < 4; j++) {
        const float4 v = samp[j * 32 + lane];
        s[2 * j]     = make_float2(v.x, v.y);
        s[2 * j + 1] = make_float2(v.z, v.w);
        float ax = cx - v.x, ay = cy - v.y;
        dc2[2 * j] = fmaf(ax, ax, ay * ay);
        ax = cx - v.z; ay = cy - v.w;
        dc2[2 * j + 1] = fmaf(ax, ax, ay * ay);
        m = fminf(m, fminf(dc2[2 * j], dc2[2 * j + 1]));
    }
    #pragma unroll
    for (int off = 16; off; off >>= 1)
        m = fminf(m, __shfl_xor_sync(0xffffffffu, m, off));
    const float dcmin = sqrtf(m);

    const int px = x0 + (lane & 7);
    const int py = y0 + (lane >> 3);
    const int p  = py * SIZE + px;

    // ---- warp-tile skip: coverage < 2.3e-5 ----
    if (dcmin > 0.115f + r) {
        out[p] = 1.0f;
        return;
    }

    // ---- warp compaction: keep dc <= dcmin + 2r + 0.055 ----
    const float thr  = dcmin + 2.0f * r + 0.055f;
    const float thr2 = thr * thr;
    float2* kp = (float2*)(keepbuf + w * KST4);
    const unsigned lt = (1u << lane) - 1u;
    int c = 0;
    #pragma unroll
    for (int j = 0; j < 8; j++) {
        const bool k = (dc2[j] <= thr2);
        const unsigned msk = __ballot_sync(0xffffffffu, k);
        if (k) kp[c + __popc(msk & lt)] = s[j];
        c += __popc(msk);
    }
    if (lane < 4) kp[c + lane] = make_float2(100.0f, 100.0f);  // sentinels
    __syncwarp();
    const int nIt = ((c + 3) & ~3) >> 1;     // float4 iterations, multiple of 2

    // ---- per-pixel single-pass soft-min, dual accumulators ----
    const float gx = (float)px * inv;
    const float gy = (float)py * inv;
    const float NEGK = -369.3298503f;        // -256 * log2(e)
    const float4* kp4 = (const float4*)kp;
    float accA = 0.0f, accB = 0.0f;
    #pragma unroll 4
    for (int i = 0; i < nIt; i++) {
        const float4 q = kp4[i];             // broadcast LDS.128
        float ax = gx - q.x, ay = gy - q.y;
        const float dA = fsqrt_approx(fmaf(ax, ax, ay * ay));
        ax = gx - q.z; ay = gy - q.w;
        const float dB = fsqrt_approx(fmaf(ax, ax, ay * ay));
        accA += fexp2_approx(dA * NEGK);
        accB += fexp2_approx(dB * NEGK);
    }

    const float md = flog2_approx(accA + accB) * (-0.69314718f / 256.0f);
    const float z  = (0.04f - md) * (200.0f * 1.44269504f);
    out[p] = frcp_approx(1.0f + fexp2_approx(z));
}

extern "C" void kernel_launch(void* const* d_in, const int* in_sizes, int n_in,
                              void* d_out, int out_size) {
    const float* cp = (const float*)d_in[0];   // control_points [8,4,2]
    float* out = (float*)d_out;
    glyph_kernel<<<2048, NT>>>(cp, out);       // 2048 CTAs x 4 warp-tiles
}